// round 1
// baseline (speedup 1.0000x reference)
#include <cuda_runtime.h>

#define N_PIX 1600
#define CCH   512
#define CORR  256
#define BATCH 16

// ---------------- scratch (static __device__ arrays; allocation-free) -------
__device__ float g_qcorr[BATCH * CORR * N_PIX];        //  26 MB
__device__ float g_ecorr[BATCH * CORR * N_PIX];        //  26 MB
__device__ float g_A    [(long)BATCH * N_PIX * N_PIX]; // 164 MB
__device__ float g_At   [(long)BATCH * N_PIX * N_PIX]; // 164 MB
__device__ float g_att_e[BATCH * CCH * N_PIX];         //  52 MB (exemplar_att)
__device__ float g_att_q[BATCH * CCH * N_PIX];         //  52 MB (query_att)
__device__ float g_wT   [2 * 9 * CCH * CCH];           //  19 MB

// ---------------- generic tiled SGEMM ---------------------------------------
// C[m,n] = sum_k A[m*sAm + k*sAk] * B[k*sBk + n]   (sBn == 1, sCn == 1)
// TM = TMR*16, TN = 64, TK = 16, 256 threads, TMRx4 micro-tile per thread.
template<int TMR>
__global__ void gemm_kernel(const float* __restrict__ A,
                            const float* __restrict__ B,
                            float* __restrict__ C,
                            int K,
                            int sAm, int sAk, long batchA,
                            int sBk, long batchB,
                            int sCm, long batchC)
{
    constexpr int TM = TMR * 16;
    constexpr int TN = 64;
    constexpr int TK = 16;
    __shared__ float As[TK][TM + 1];
    __shared__ float Bs[TK][TN];

    const int b = blockIdx.z;
    A += (long)b * batchA;
    B += (long)b * batchB;
    C += (long)b * batchC;

    const int m0 = blockIdx.y * TM;
    const int n0 = blockIdx.x * TN;
    const int tid = threadIdx.x;
    const int tx = tid & 15;
    const int ty = tid >> 4;

    float acc[TMR][4];
#pragma unroll
    for (int i = 0; i < TMR; i++)
#pragma unroll
        for (int j = 0; j < 4; j++) acc[i][j] = 0.f;

    for (int k0 = 0; k0 < K; k0 += TK) {
        if (sAk == 1) {
            // k is contiguous in A: read kk-fast (coalesced), padded smem kills conflicts
#pragma unroll
            for (int r = 0; r < TM * TK / 256; r++) {
                int i  = tid + r * 256;
                int kk = i & (TK - 1);
                int mm = i >> 4;
                As[kk][mm] = A[(long)(m0 + mm) * sAm + (k0 + kk)];
            }
        } else {
            // m is contiguous in A: read mm-fast (coalesced)
#pragma unroll
            for (int r = 0; r < TM * TK / 256; r++) {
                int i  = tid + r * 256;
                int mm = i & (TM - 1);
                int kk = i / TM;
                As[kk][mm] = A[(long)(m0 + mm) * sAm + (long)(k0 + kk) * sAk];
            }
        }
#pragma unroll
        for (int r = 0; r < TN * TK / 256; r++) {
            int i  = tid + r * 256;
            int nn = i & 63;
            int kk = i >> 6;
            Bs[kk][nn] = B[(long)(k0 + kk) * sBk + (n0 + nn)];
        }
        __syncthreads();

#pragma unroll
        for (int kk = 0; kk < TK; kk++) {
            float a[TMR];
#pragma unroll
            for (int i = 0; i < TMR; i++) a[i] = As[kk][ty * TMR + i];
            float4 b4 = *(const float4*)&Bs[kk][tx * 4];
#pragma unroll
            for (int i = 0; i < TMR; i++) {
                acc[i][0] += a[i] * b4.x;
                acc[i][1] += a[i] * b4.y;
                acc[i][2] += a[i] * b4.z;
                acc[i][3] += a[i] * b4.w;
            }
        }
        __syncthreads();
    }

#pragma unroll
    for (int i = 0; i < TMR; i++) {
        *(float4*)&C[(long)(m0 + ty * TMR + i) * sCm + n0 + tx * 4] =
            make_float4(acc[i][0], acc[i][1], acc[i][2], acc[i][3]);
    }
}

// ---------------- batched 1600x1600 transpose -------------------------------
__global__ void transpose_kernel(const float* __restrict__ src,
                                 float* __restrict__ dst)
{
    __shared__ float tile[32][33];
    const long off = (long)blockIdx.z * N_PIX * N_PIX;
    const float* s = src + off;
    float* d = dst + off;
    const int x0 = blockIdx.x * 32, y0 = blockIdx.y * 32;
    const int tx = threadIdx.x, ty = threadIdx.y;   // (32, 8)
#pragma unroll
    for (int r = 0; r < 32; r += 8)
        tile[ty + r][tx] = s[(long)(y0 + ty + r) * N_PIX + x0 + tx];
    __syncthreads();
#pragma unroll
    for (int r = 0; r < 32; r += 8)
        d[(long)(x0 + ty + r) * N_PIX + y0 + tx] = tile[tx][ty + r];
}

// ---------------- in-place row softmax (applied to g_A and g_At) ------------
__global__ void row_softmax_kernel(float* __restrict__ A1, float* __restrict__ A2)
{
    float* base = blockIdx.y ? A2 : A1;
    float* row = base + (long)blockIdx.x * N_PIX;
    const int tid = threadIdx.x;   // 256

    float vals[7];
    float mx = -1e30f;
    int cnt = 0;
    for (int i = tid; i < N_PIX; i += 256) {
        float v = row[i];
        vals[cnt++] = v;
        mx = fmaxf(mx, v);
    }
    __shared__ float red[256];
    red[tid] = mx;
    __syncthreads();
    for (int s = 128; s > 0; s >>= 1) {
        if (tid < s) red[tid] = fmaxf(red[tid], red[tid + s]);
        __syncthreads();
    }
    mx = red[0];
    __syncthreads();

    float sum = 0.f;
    for (int k = 0; k < cnt; k++) {
        vals[k] = __expf(vals[k] - mx);
        sum += vals[k];
    }
    red[tid] = sum;
    __syncthreads();
    for (int s = 128; s > 0; s >>= 1) {
        if (tid < s) red[tid] += red[tid + s];
        __syncthreads();
    }
    const float inv = 1.f / red[0];

    cnt = 0;
    for (int i = tid; i < N_PIX; i += 256) row[i] = vals[cnt++] * inv;
}

// ---------------- conv weight re-layout: OIHW -> [which][kyx][c][o] ---------
__global__ void wtrans_kernel(const float* __restrict__ w1,
                              const float* __restrict__ w2,
                              float* __restrict__ wT)
{
    long idx = (long)blockIdx.x * 256 + threadIdx.x;
    const long per = (long)CCH * CCH * 9;
    if (idx >= 2 * per) return;
    int which = (int)(idx / per);
    long r   = idx % per;
    int kyx  = (int)(r / ((long)CCH * CCH));
    long r2  = r % ((long)CCH * CCH);
    int c    = (int)(r2 / CCH);
    int o    = (int)(r2 % CCH);
    const float* w = which ? w2 : w1;
    wT[idx] = w[((long)o * CCH + c) * 9 + kyx];
}

// ---------------- 3x3 SAME conv as 9 shifted implicit GEMMs -----------------
// grid: (25, 4, 32). z = batch + 16*which. TM=128 out-channels, TN=64 pixels.
__global__ void conv3x3_kernel(const float* __restrict__ in_e,
                               const float* __restrict__ in_q,
                               const float* __restrict__ wT,
                               float* __restrict__ out)
{
    constexpr int TM = 128, TN = 64, TK = 16;
    __shared__ float As[TK][TM + 1];
    __shared__ float Bs[TK][TN];

    const int z = blockIdx.z;
    const int b = z & 15;
    const int which = z >> 4;   // 0: exemplar_att * w_c1 -> ch [0,512); 1: query_att * w_c2
    const float* inp = (which ? in_q : in_e) + (long)b * CCH * N_PIX;
    const float* w   = wT + (long)which * 9 * CCH * CCH;
    float* outp = out + ((long)b * 2 * CCH + (long)which * CCH) * N_PIX;

    const int m0 = blockIdx.y * TM;
    const int n0 = blockIdx.x * TN;
    const int tid = threadIdx.x;
    const int tx = tid & 15;
    const int ty = tid >> 4;

    // per-thread pixel coords for the 4 B-tile elements it loads each chunk
    int py[4], px[4], pnn[4];
#pragma unroll
    for (int r = 0; r < 4; r++) {
        int i = tid + r * 256;
        int nn = i & 63;
        int p = n0 + nn;
        pnn[r] = nn;
        py[r] = p / 40;
        px[r] = p % 40;
    }

    float acc[8][4];
#pragma unroll
    for (int i = 0; i < 8; i++)
#pragma unroll
        for (int j = 0; j < 4; j++) acc[i][j] = 0.f;

    for (int kyx = 0; kyx < 9; kyx++) {
        const int dy = kyx / 3 - 1;
        const int dx = kyx % 3 - 1;
        const float* wk = w + (long)kyx * CCH * CCH;   // [c][o]

        for (int c0 = 0; c0 < CCH; c0 += TK) {
#pragma unroll
            for (int r = 0; r < 8; r++) {
                int i  = tid + r * 256;
                int mm = i & 127;
                int kk = i >> 7;
                As[kk][mm] = wk[(long)(c0 + kk) * CCH + m0 + mm];
            }
#pragma unroll
            for (int r = 0; r < 4; r++) {
                int i  = tid + r * 256;
                int kk = i >> 6;
                int ys = py[r] + dy;
                int xs = px[r] + dx;
                float v = 0.f;
                if ((unsigned)ys < 40u && (unsigned)xs < 40u)
                    v = inp[(long)(c0 + kk) * N_PIX + ys * 40 + xs];
                Bs[kk][pnn[r]] = v;
            }
            __syncthreads();

#pragma unroll
            for (int kk = 0; kk < TK; kk++) {
                float a[8];
#pragma unroll
                for (int i = 0; i < 8; i++) a[i] = As[kk][ty * 8 + i];
                float4 b4 = *(const float4*)&Bs[kk][tx * 4];
#pragma unroll
                for (int i = 0; i < 8; i++) {
                    acc[i][0] += a[i] * b4.x;
                    acc[i][1] += a[i] * b4.y;
                    acc[i][2] += a[i] * b4.z;
                    acc[i][3] += a[i] * b4.w;
                }
            }
            __syncthreads();
        }
    }

#pragma unroll
    for (int i = 0; i < 8; i++) {
        *(float4*)&outp[(long)(m0 + ty * 8 + i) * N_PIX + n0 + tx * 4] =
            make_float4(acc[i][0], acc[i][1], acc[i][2], acc[i][3]);
    }
}

// ---------------- launch -----------------------------------------------------
extern "C" void kernel_launch(void* const* d_in, const int* in_sizes, int n_in,
                              void* d_out, int out_size)
{
    const float* exemplar = (const float*)d_in[0];
    const float* query    = (const float*)d_in[1];
    const float* w_e      = (const float*)d_in[2];
    const float* w_q      = (const float*)d_in[3];
    const float* w_c1     = (const float*)d_in[4];
    const float* w_c2     = (const float*)d_in[5];
    float* out = (float*)d_out;

    float *qcorr, *ecorr, *Abuf, *Atbuf, *att_e, *att_q, *wT;
    cudaGetSymbolAddress((void**)&qcorr, g_qcorr);
    cudaGetSymbolAddress((void**)&ecorr, g_ecorr);
    cudaGetSymbolAddress((void**)&Abuf,  g_A);
    cudaGetSymbolAddress((void**)&Atbuf, g_At);
    cudaGetSymbolAddress((void**)&att_e, g_att_e);
    cudaGetSymbolAddress((void**)&att_q, g_att_q);
    cudaGetSymbolAddress((void**)&wT,    g_wT);

    // conv weights OIHW -> [which][kyx][c][o]
    {
        long total = 2L * 9 * CCH * CCH;
        wtrans_kernel<<<(unsigned)((total + 255) / 256), 256>>>(w_c1, w_c2, wT);
    }

    // 1x1 projections: corr[b,o,n] = sum_c w[o,c] * in[b,c,n]
    gemm_kernel<8><<<dim3(25, CORR / 128, BATCH), 256>>>(
        w_q, query, qcorr, CCH,
        CCH, 1, 0L,
        N_PIX, (long)CCH * N_PIX,
        N_PIX, (long)CORR * N_PIX);
    gemm_kernel<8><<<dim3(25, CORR / 128, BATCH), 256>>>(
        w_e, exemplar, ecorr, CCH,
        CCH, 1, 0L,
        N_PIX, (long)CCH * N_PIX,
        N_PIX, (long)CORR * N_PIX);

    // A[b,n,m] = sum_k ecorr[b,k,n] * qcorr[b,k,m]
    gemm_kernel<4><<<dim3(25, 25, BATCH), 256>>>(
        ecorr, qcorr, Abuf, CORR,
        1, N_PIX, (long)CORR * N_PIX,
        N_PIX, (long)CORR * N_PIX,
        N_PIX, (long)N_PIX * N_PIX);

    // At = A^T per batch
    transpose_kernel<<<dim3(50, 50, BATCH), dim3(32, 8)>>>(Abuf, Atbuf);

    // row softmax: Abuf -> softmax(A, axis=2) == Bm ; Atbuf -> S1^T
    row_softmax_kernel<<<dim3(BATCH * N_PIX, 2), 256>>>(Abuf, Atbuf);

    // exemplar_att[b,c,m] = sum_n query[b,c,n] * Bm[b,n,m]
    gemm_kernel<8><<<dim3(25, CCH / 128, BATCH), 256>>>(
        query, Abuf, att_e, N_PIX,
        N_PIX, 1, (long)CCH * N_PIX,
        N_PIX, (long)N_PIX * N_PIX,
        N_PIX, (long)CCH * N_PIX);

    // query_att[b,c,j] = sum_i exemplar[b,c,i] * S1t[b,i,j]
    gemm_kernel<8><<<dim3(25, CCH / 128, BATCH), 256>>>(
        exemplar, Atbuf, att_q, N_PIX,
        N_PIX, 1, (long)CCH * N_PIX,
        N_PIX, (long)N_PIX * N_PIX,
        N_PIX, (long)CCH * N_PIX);

    // 3x3 SAME convs into concatenated output
    conv3x3_kernel<<<dim3(25, CCH / 128, 2 * BATCH), 256>>>(att_e, att_q, wT, out);
}

// round 3
// speedup vs baseline: 3.2530x; 3.2530x over previous
#include <cuda_runtime.h>
#include <cstdint>

#define N_PIX 1600
#define CCH   512
#define CORR  256
#define BATCH 16

// ---------------- scratch (static __device__ arrays; allocation-free) -------
__device__ float g_inTe  [BATCH * N_PIX * CCH];            // exemplar^T [p][c]
__device__ float g_inTq  [BATCH * N_PIX * CCH];            // query^T    [p][c]
__device__ float g_qcorr [BATCH * N_PIX * CORR];           // [b][p][o]
__device__ float g_ecorr [BATCH * N_PIX * CORR];           // [b][p][o]
__device__ float g_E     [(long)BATCH * N_PIX * N_PIX];    // exp(A)   164 MB
__device__ float g_Et    [(long)BATCH * N_PIX * N_PIX];    // exp(A)^T 164 MB
__device__ float g_rsE   [BATCH * N_PIX];                  // rowsum(E)
__device__ float g_rsEt  [BATCH * N_PIX];                  // colsum(E)
__device__ float g_esc   [BATCH * CCH * N_PIX];            // exemplar * inv colsum
__device__ float g_qsc   [BATCH * CCH * N_PIX];            // query    * inv rowsum
__device__ float g_att_e [BATCH * CCH * N_PIX];
__device__ float g_att_q [BATCH * CCH * N_PIX];
__device__ float g_attTe [BATCH * N_PIX * CCH];
__device__ float g_attTq [BATCH * N_PIX * CCH];
__device__ float g_wT    [2 * 9 * CCH * CCH];              // [which][kyx][o][c]

// ---------------- mma.sync tf32 helpers --------------------------------------
__device__ __forceinline__ void mma8(float4& d, const uint32_t a[4],
                                     const uint32_t b[2]) {
    asm volatile(
        "mma.sync.aligned.m16n8k8.row.col.f32.tf32.tf32.f32 "
        "{%0,%1,%2,%3}, {%4,%5,%6,%7}, {%8,%9}, {%0,%1,%2,%3};"
        : "+f"(d.x), "+f"(d.y), "+f"(d.z), "+f"(d.w)
        : "r"(a[0]), "r"(a[1]), "r"(a[2]), "r"(a[3]), "r"(b[0]), "r"(b[1]));
}
__device__ __forceinline__ float4 cvt4(float4 v) {
    asm("cvt.rna.tf32.f32 %0, %0;" : "+f"(v.x));
    asm("cvt.rna.tf32.f32 %0, %0;" : "+f"(v.y));
    asm("cvt.rna.tf32.f32 %0, %0;" : "+f"(v.z));
    asm("cvt.rna.tf32.f32 %0, %0;" : "+f"(v.w));
    return v;
}

#define LDPAD 36   // smem row stride (floats): conflict-free (4r+c is a permutation)

// ---------------- tf32 GEMM: C[m][n] = sum_k A[m][k] * B[n][k] ---------------
// A:[MA][K] row-major, B:[NB][K] row-major, both K-contiguous, lda=ldb=K.
// CTA tile 128x128xK32, 8 warps (2x4), warp tile 64x32.
template<bool DO_EXP>
__global__ void __launch_bounds__(256, 2)
gemm_mma(const float* __restrict__ A, const float* __restrict__ B,
         float* __restrict__ C, int K, int MA, int NB, int ldc,
         long bA, long bB, long bC)
{
    __shared__ float As[128 * LDPAD];
    __shared__ float Bs[128 * LDPAD];
    const int tid = threadIdx.x;
    const int lane = tid & 31, wid = tid >> 5;
    const int wm = wid >> 2, wn = wid & 3;
    const int lg = lane >> 2, lt = lane & 3;   // groupID, threadID_in_group
    A += (long)blockIdx.z * bA;
    B += (long)blockIdx.z * bB;
    C += (long)blockIdx.z * bC;
    const int m0 = blockIdx.y * 128, n0 = blockIdx.x * 128;

    float4 acc[4][4];
#pragma unroll
    for (int i = 0; i < 4; i++)
#pragma unroll
        for (int j = 0; j < 4; j++) acc[i][j] = make_float4(0.f, 0.f, 0.f, 0.f);

    const int lr = tid >> 2;   // row base 0..63 (also +64)
    const int lq = tid & 3;    // float4 col (also +4)

    for (int k0 = 0; k0 < K; k0 += 32) {
#pragma unroll
        for (int h = 0; h < 2; h++) {
            const int row = lr + h * 64;
            const int gm = m0 + row, gn = n0 + row;
#pragma unroll
            for (int q = 0; q < 2; q++) {
                const int c4 = lq + q * 4;
                float4 va = make_float4(0.f, 0.f, 0.f, 0.f);
                float4 vb = make_float4(0.f, 0.f, 0.f, 0.f);
                if (gm < MA) va = *(const float4*)(A + (long)gm * K + k0 + c4 * 4);
                if (gn < NB) vb = *(const float4*)(B + (long)gn * K + k0 + c4 * 4);
                *(float4*)(As + row * LDPAD + c4 * 4) = cvt4(va);
                *(float4*)(Bs + row * LDPAD + c4 * 4) = cvt4(vb);
            }
        }
        __syncthreads();
#pragma unroll
        for (int ks = 0; ks < 4; ks++) {
            uint32_t af[4][4], bf[4][2];
#pragma unroll
            for (int mt = 0; mt < 4; mt++) {
                const float* p = As + (wm * 64 + mt * 16 + lg) * LDPAD + ks * 8 + lt;
                af[mt][0] = __float_as_uint(p[0]);
                af[mt][1] = __float_as_uint(p[8 * LDPAD]);
                af[mt][2] = __float_as_uint(p[4]);
                af[mt][3] = __float_as_uint(p[8 * LDPAD + 4]);
            }
#pragma unroll
            for (int nt = 0; nt < 4; nt++) {
                const float* p = Bs + (wn * 32 + nt * 8 + lg) * LDPAD + ks * 8 + lt;
                bf[nt][0] = __float_as_uint(p[0]);
                bf[nt][1] = __float_as_uint(p[4]);
            }
#pragma unroll
            for (int mt = 0; mt < 4; mt++)
#pragma unroll
                for (int nt = 0; nt < 4; nt++) mma8(acc[mt][nt], af[mt], bf[nt]);
        }
        __syncthreads();
    }
#pragma unroll
    for (int mt = 0; mt < 4; mt++) {
        const int r = m0 + wm * 64 + mt * 16 + lg;
#pragma unroll
        for (int nt = 0; nt < 4; nt++) {
            const int n = n0 + wn * 32 + nt * 8 + 2 * lt;
            float4 v = acc[mt][nt];
            if (DO_EXP) {
                v.x = __expf(v.x); v.y = __expf(v.y);
                v.z = __expf(v.z); v.w = __expf(v.w);
            }
            if (n < NB) {
                if (r < MA)
                    *(float2*)(C + (long)r * ldc + n) = make_float2(v.x, v.y);
                if (r + 8 < MA)
                    *(float2*)(C + (long)(r + 8) * ldc + n) = make_float2(v.z, v.w);
            }
        }
    }
}

// ---------------- conv 3x3 SAME via implicit GEMM (mma.sync tf32) ------------
// out[o][p] = sum_{kyx,c} wT[which][kyx][o][c] * inT[p+shift][c]
__global__ void __launch_bounds__(256, 2)
conv_mma(const float* __restrict__ attTe, const float* __restrict__ attTq,
         const float* __restrict__ wT, float* __restrict__ out)
{
    __shared__ float As[128 * LDPAD];
    __shared__ float Bs[128 * LDPAD];
    const int tid = threadIdx.x;
    const int lane = tid & 31, wid = tid >> 5;
    const int wm = wid >> 2, wn = wid & 3;
    const int lg = lane >> 2, lt = lane & 3;
    const int z = blockIdx.z;
    const int b = z & 15, which = z >> 4;
    const float* inT = (which ? attTq : attTe) + (long)b * N_PIX * CCH;
    const float* wbase = wT + (long)which * 9 * CCH * CCH;
    const int m0 = blockIdx.y * 128;   // out channel block (exact, 512)
    const int n0 = blockIdx.x * 128;   // pixel block (1664 covers 1600, guarded)

    const int lr = tid >> 2;
    const int lq = tid & 3;
    int py[2], px[2]; bool pv[2];
#pragma unroll
    for (int h = 0; h < 2; h++) {
        const int p = n0 + lr + h * 64;
        py[h] = p / 40; px[h] = p % 40;
        pv[h] = (p < N_PIX);
    }

    float4 acc[4][4];
#pragma unroll
    for (int i = 0; i < 4; i++)
#pragma unroll
        for (int j = 0; j < 4; j++) acc[i][j] = make_float4(0.f, 0.f, 0.f, 0.f);

    for (int ck = 0; ck < 144; ck++) {
        const int kyx = ck >> 4;
        const int cc = (ck & 15) * 32;
        const int dy = kyx / 3 - 1, dx = kyx % 3 - 1;
        const float* wk = wbase + (long)kyx * CCH * CCH;
#pragma unroll
        for (int h = 0; h < 2; h++) {
            const int row = lr + h * 64;
            const int ys = py[h] + dy, xs = px[h] + dx;
            const bool ok = pv[h] && (unsigned)ys < 40u && (unsigned)xs < 40u;
            const float* bp = inT + (long)(ys * 40 + xs) * CCH + cc;
            const float* ap = wk + (long)(m0 + row) * CCH + cc;
#pragma unroll
            for (int q = 0; q < 2; q++) {
                const int c4 = lq + q * 4;
                float4 vb = make_float4(0.f, 0.f, 0.f, 0.f);
                if (ok) vb = *(const float4*)(bp + c4 * 4);
                float4 va = *(const float4*)(ap + c4 * 4);
                *(float4*)(As + row * LDPAD + c4 * 4) = cvt4(va);
                *(float4*)(Bs + row * LDPAD + c4 * 4) = cvt4(vb);
            }
        }
        __syncthreads();
#pragma unroll
        for (int ks = 0; ks < 4; ks++) {
            uint32_t af[4][4], bf[4][2];
#pragma unroll
            for (int mt = 0; mt < 4; mt++) {
                const float* p = As + (wm * 64 + mt * 16 + lg) * LDPAD + ks * 8 + lt;
                af[mt][0] = __float_as_uint(p[0]);
                af[mt][1] = __float_as_uint(p[8 * LDPAD]);
                af[mt][2] = __float_as_uint(p[4]);
                af[mt][3] = __float_as_uint(p[8 * LDPAD + 4]);
            }
#pragma unroll
            for (int nt = 0; nt < 4; nt++) {
                const float* p = Bs + (wn * 32 + nt * 8 + lg) * LDPAD + ks * 8 + lt;
                bf[nt][0] = __float_as_uint(p[0]);
                bf[nt][1] = __float_as_uint(p[4]);
            }
#pragma unroll
            for (int mt = 0; mt < 4; mt++)
#pragma unroll
                for (int nt = 0; nt < 4; nt++) mma8(acc[mt][nt], af[mt], bf[nt]);
        }
        __syncthreads();
    }

    float* obase = out + ((long)b * 2 * CCH + (long)which * CCH) * N_PIX;
#pragma unroll
    for (int mt = 0; mt < 4; mt++) {
        const int r = m0 + wm * 64 + mt * 16 + lg;
#pragma unroll
        for (int nt = 0; nt < 4; nt++) {
            const int n = n0 + wn * 32 + nt * 8 + 2 * lt;
            if (n < N_PIX) {
                float4 v = acc[mt][nt];
                *(float2*)(obase + (long)r * N_PIX + n) = make_float2(v.x, v.y);
                *(float2*)(obase + (long)(r + 8) * N_PIX + n) = make_float2(v.z, v.w);
            }
        }
    }
}

// ---------------- generic batched transpose (R,C multiples of 32) -----------
__global__ void transpose_kernel(const float* __restrict__ src,
                                 float* __restrict__ dst,
                                 int R, int C, long sstride, long dstride)
{
    __shared__ float t[32][33];
    src += (long)blockIdx.z * sstride;
    dst += (long)blockIdx.z * dstride;
    const int x0 = blockIdx.x * 32, y0 = blockIdx.y * 32;
    const int tx = threadIdx.x, ty = threadIdx.y;   // (32, 8)
#pragma unroll
    for (int r = 0; r < 32; r += 8)
        t[ty + r][tx] = src[(long)(y0 + ty + r) * C + x0 + tx];
    __syncthreads();
#pragma unroll
    for (int r = 0; r < 32; r += 8)
        dst[(long)(x0 + ty + r) * R + y0 + tx] = t[tx][ty + r];
}

// ---------------- row sums of E and Et ---------------------------------------
__global__ void rowsum_kernel(const float* __restrict__ E,
                              const float* __restrict__ Et,
                              float* __restrict__ rsE, float* __restrict__ rsEt)
{
    const long NN = (long)N_PIX * N_PIX;
    const float* src = (blockIdx.y ? Et : E) + (long)blockIdx.z * NN
                       + (long)blockIdx.x * N_PIX;
    float* dst = (blockIdx.y ? rsEt : rsE) + blockIdx.z * N_PIX + blockIdx.x;
    const int tid = threadIdx.x;   // 256
    float s = 0.f;
    for (int i = tid; i < N_PIX; i += 256) s += src[i];
    __shared__ float red[256];
    red[tid] = s;
    __syncthreads();
    for (int st = 128; st > 0; st >>= 1) {
        if (tid < st) red[tid] += red[tid + st];
        __syncthreads();
    }
    if (tid == 0) *dst = red[0];
}

__global__ void inv_kernel(float* __restrict__ a, float* __restrict__ b, int n)
{
    int i = blockIdx.x * 256 + threadIdx.x;
    if (i < n) { a[i] = 1.f / a[i]; b[i] = 1.f / b[i]; }
}

// esc[b][c][i] = exemplar * invColsum(E)[i] ; qsc = query * invRowsum(E)[i]
__global__ void scale_kernel(const float* __restrict__ ex,
                             const float* __restrict__ qu,
                             const float* __restrict__ invCs,
                             const float* __restrict__ invRs,
                             float* __restrict__ e2, float* __restrict__ q2)
{
    long idx = (long)blockIdx.x * 256 + threadIdx.x;
    if (idx >= (long)BATCH * CCH * N_PIX) return;
    int i = (int)(idx % N_PIX);
    int b = (int)(idx / ((long)CCH * N_PIX));
    e2[idx] = ex[idx] * invCs[b * N_PIX + i];
    q2[idx] = qu[idx] * invRs[b * N_PIX + i];
}

// ---------------- conv weights OIHW -> [which][kyx][o][c] --------------------
__global__ void wtrans_kernel(const float* __restrict__ w1,
                              const float* __restrict__ w2,
                              float* __restrict__ wT)
{
    long idx = (long)blockIdx.x * 256 + threadIdx.x;
    const long per = 9L * CCH * CCH;
    if (idx >= 2 * per) return;
    int c = (int)(idx & (CCH - 1));
    long t = idx >> 9;
    int o = (int)(t & (CCH - 1));
    long t2 = t >> 9;
    int kyx = (int)(t2 % 9);
    int which = (int)(t2 / 9);
    const float* w = which ? w2 : w1;
    wT[idx] = w[((long)o * CCH + c) * 9 + kyx];
}

// ---------------- launch ------------------------------------------------------
extern "C" void kernel_launch(void* const* d_in, const int* in_sizes, int n_in,
                              void* d_out, int out_size)
{
    const float* exemplar = (const float*)d_in[0];
    const float* query    = (const float*)d_in[1];
    const float* w_e      = (const float*)d_in[2];
    const float* w_q      = (const float*)d_in[3];
    const float* w_c1     = (const float*)d_in[4];
    const float* w_c2     = (const float*)d_in[5];
    float* out = (float*)d_out;

    float *inTe, *inTq, *qcorr, *ecorr, *E, *Et, *rsE, *rsEt,
          *esc, *qsc, *att_e, *att_q, *attTe, *attTq, *wT;
    cudaGetSymbolAddress((void**)&inTe,  g_inTe);
    cudaGetSymbolAddress((void**)&inTq,  g_inTq);
    cudaGetSymbolAddress((void**)&qcorr, g_qcorr);
    cudaGetSymbolAddress((void**)&ecorr, g_ecorr);
    cudaGetSymbolAddress((void**)&E,     g_E);
    cudaGetSymbolAddress((void**)&Et,    g_Et);
    cudaGetSymbolAddress((void**)&rsE,   g_rsE);
    cudaGetSymbolAddress((void**)&rsEt,  g_rsEt);
    cudaGetSymbolAddress((void**)&esc,   g_esc);
    cudaGetSymbolAddress((void**)&qsc,   g_qsc);
    cudaGetSymbolAddress((void**)&att_e, g_att_e);
    cudaGetSymbolAddress((void**)&att_q, g_att_q);
    cudaGetSymbolAddress((void**)&attTe, g_attTe);
    cudaGetSymbolAddress((void**)&attTq, g_attTq);
    cudaGetSymbolAddress((void**)&wT,    g_wT);

    const long NN = (long)N_PIX * N_PIX;
    const long CN = (long)CCH * N_PIX;
    const long NK = (long)N_PIX * CORR;

    // weight re-layout for conv
    wtrans_kernel<<<(unsigned)((2L * 9 * CCH * CCH + 255) / 256), 256>>>(w_c1, w_c2, wT);

    // input transposes [c][p] -> [p][c]
    transpose_kernel<<<dim3(50, 16, BATCH), dim3(32, 8)>>>(exemplar, inTe,
                                                           CCH, N_PIX, CN, CN);
    transpose_kernel<<<dim3(50, 16, BATCH), dim3(32, 8)>>>(query, inTq,
                                                           CCH, N_PIX, CN, CN);

    // 1x1 projections: corr[p][o] = sum_c inT[p][c] * w[o][c]
    gemm_mma<false><<<dim3(2, 13, BATCH), 256>>>(
        inTq, w_q, qcorr, CCH, N_PIX, CORR, CORR, CN, 0L, NK);
    gemm_mma<false><<<dim3(2, 13, BATCH), 256>>>(
        inTe, w_e, ecorr, CCH, N_PIX, CORR, CORR, CN, 0L, NK);

    // E[n][m] = exp( sum_k ecorr[n][k] * qcorr[m][k] )
    gemm_mma<true><<<dim3(13, 13, BATCH), 256>>>(
        ecorr, qcorr, E, CORR, N_PIX, N_PIX, N_PIX, NK, NK, NN);

    // Et = E^T
    transpose_kernel<<<dim3(50, 50, BATCH), dim3(32, 8)>>>(E, Et,
                                                           N_PIX, N_PIX, NN, NN);

    // row sums -> inverses -> scaled inputs
    rowsum_kernel<<<dim3(N_PIX, 2, BATCH), 256>>>(E, Et, rsE, rsEt);
    inv_kernel<<<(BATCH * N_PIX + 255) / 256, 256>>>(rsE, rsEt, BATCH * N_PIX);
    scale_kernel<<<(unsigned)(((long)BATCH * CCH * N_PIX + 255) / 256), 256>>>(
        exemplar, query, rsEt, rsE, esc, qsc);

    // query_att[c][j]    = sum_i esc[c][i] * E[j][i]
    gemm_mma<false><<<dim3(13, 4, BATCH), 256>>>(
        esc, E, att_q, N_PIX, CCH, N_PIX, N_PIX, CN, NN, CN);
    // exemplar_att[c][j] = sum_i qsc[c][i] * Et[j][i]
    gemm_mma<false><<<dim3(13, 4, BATCH), 256>>>(
        qsc, Et, att_e, N_PIX, CCH, N_PIX, N_PIX, CN, NN, CN);

    // transpose attention outputs to [pixel][channel] for conv
    transpose_kernel<<<dim3(50, 16, BATCH), dim3(32, 8)>>>(att_e, attTe,
                                                           CCH, N_PIX, CN, CN);
    transpose_kernel<<<dim3(50, 16, BATCH), dim3(32, 8)>>>(att_q, attTq,
                                                           CCH, N_PIX, CN, CN);

    // 3x3 SAME convs into concatenated output
    conv_mma<<<dim3(13, 4, 2 * BATCH), 256>>>(attTe, attTq, wT, out);
}

// round 4
// speedup vs baseline: 3.9535x; 1.2154x over previous
#include <cuda_runtime.h>
#include <cstdint>

#define N_PIX 1600
#define CCH   512
#define CORR  256
#define BATCH 16

// ---------------- scratch (static __device__ arrays; allocation-free) -------
__device__ float g_inTe  [BATCH * N_PIX * CCH];            // exemplar^T [p][c] (tf32)
__device__ float g_inTq  [BATCH * N_PIX * CCH];            // query^T    [p][c] (tf32)
__device__ float g_qcorr [BATCH * N_PIX * CORR];           // (tf32)
__device__ float g_ecorr [BATCH * N_PIX * CORR];           // (tf32)
__device__ float g_E     [(long)BATCH * N_PIX * N_PIX];    // exp(A) (tf32)
__device__ float g_Et    [(long)BATCH * N_PIX * N_PIX];    // E^T    (tf32)
__device__ float g_rsE   [BATCH * N_PIX];
__device__ float g_rsEt  [BATCH * N_PIX];
__device__ float g_esc   [BATCH * CCH * N_PIX];            // (tf32)
__device__ float g_qsc   [BATCH * CCH * N_PIX];            // (tf32)
__device__ float g_att_e [BATCH * CCH * N_PIX];
__device__ float g_att_q [BATCH * CCH * N_PIX];
__device__ float g_attTe [BATCH * N_PIX * CCH];            // (tf32)
__device__ float g_attTq [BATCH * N_PIX * CCH];            // (tf32)
__device__ float g_wT    [2 * 9 * CCH * CCH];              // [which][kyx][o][c] (tf32)
__device__ float g_w1    [2 * CORR * CCH];                 // [which][o][c] (tf32)

// ---------------- helpers -----------------------------------------------------
__device__ __forceinline__ void mma8(float4& d, const uint32_t a[4],
                                     const uint32_t b[2]) {
    asm volatile(
        "mma.sync.aligned.m16n8k8.row.col.f32.tf32.tf32.f32 "
        "{%0,%1,%2,%3}, {%4,%5,%6,%7}, {%8,%9}, {%0,%1,%2,%3};"
        : "+f"(d.x), "+f"(d.y), "+f"(d.z), "+f"(d.w)
        : "r"(a[0]), "r"(a[1]), "r"(a[2]), "r"(a[3]), "r"(b[0]), "r"(b[1]));
}
__device__ __forceinline__ float cvt1(float v) {
    asm("cvt.rna.tf32.f32 %0, %0;" : "+f"(v));
    return v;
}
__device__ __forceinline__ float4 cvt4(float4 v) {
    v.x = cvt1(v.x); v.y = cvt1(v.y); v.z = cvt1(v.z); v.w = cvt1(v.w);
    return v;
}
__device__ __forceinline__ uint32_t s2u(const void* p) {
    return (uint32_t)__cvta_generic_to_shared(p);
}
__device__ __forceinline__ void cpasync16(uint32_t dst, const void* src,
                                          uint32_t sz) {
    asm volatile("cp.async.cg.shared.global [%0], [%1], 16, %2;"
                 :: "r"(dst), "l"(src), "r"(sz));
}
#define CP_COMMIT() asm volatile("cp.async.commit_group;" ::: "memory")
#define CP_WAIT(n)  asm volatile("cp.async.wait_group %0;" :: "n"(n) : "memory")

// smem geometry (floats)
#define PITCH    36
#define A_FL     (128 * PITCH)           // 4608
#define B_FL     (256 * PITCH)           // 9216
#define STAGE_FL (A_FL + B_FL)           // 13824
#define STAGE_B  (STAGE_FL * 4)          // 55296
#define SMEM_B   (2 * STAGE_B)           // 110592

// ---------------- tf32 GEMM: C[m][n] = sum_k A[m][k]*B[n][k] ------------------
// CTA 128x256xK32, 8 warps (2x4), warp tile 64x64, cp.async double buffer.
// Operands must already be tf32-rounded. Output always tf32-rounded.
template<bool DO_EXP>
__global__ void __launch_bounds__(256, 1)
gemm_mma(const float* __restrict__ A, const float* __restrict__ B,
         float* __restrict__ C, int K, int MA, int NB, int ldc,
         long bA, long bB, long bC)
{
    extern __shared__ float sm[];
    const uint32_t smb = s2u(sm);
    const int tid = threadIdx.x;
    const int lane = tid & 31, wid = tid >> 5;
    const int wm = wid >> 2, wn = wid & 3;
    const int lg = lane >> 2, lt = lane & 3;
    A += (long)blockIdx.z * bA;
    B += (long)blockIdx.z * bB;
    C += (long)blockIdx.z * bC;
    const int m0 = blockIdx.y * 128, n0 = blockIdx.x * 256;

    // per-thread load slots
    const int lrow = tid >> 3;        // 0..31 base row (A: +32*it(4), B: +32*it(8))
    const int lf4  = tid & 7;

    // gmem pointers and predicates
    const float* aptr[4];
    uint32_t asz[4], adst[4];
#pragma unroll
    for (int it = 0; it < 4; it++) {
        int row = lrow + it * 32;
        aptr[it] = A + (long)(m0 + row) * K + lf4 * 4;
        asz[it] = (m0 + row) < MA ? 16u : 0u;
        adst[it] = row * (PITCH * 4) + lf4 * 16;
    }
    const float* bptr[8];
    uint32_t bsz[8], bdst[8];
#pragma unroll
    for (int it = 0; it < 8; it++) {
        int row = lrow + it * 32;
        bptr[it] = B + (long)(n0 + row) * K + lf4 * 4;
        bsz[it] = (n0 + row) < NB ? 16u : 0u;
        bdst[it] = A_FL * 4 + row * (PITCH * 4) + lf4 * 16;
    }

    float4 acc[4][8];
#pragma unroll
    for (int i = 0; i < 4; i++)
#pragma unroll
        for (int j = 0; j < 8; j++) acc[i][j] = make_float4(0.f, 0.f, 0.f, 0.f);

    const int nk = K >> 5;

    // prologue: stage 0 <- ck 0
    {
        uint32_t sa = smb;
#pragma unroll
        for (int it = 0; it < 4; it++) cpasync16(sa + adst[it], aptr[it], asz[it]);
#pragma unroll
        for (int it = 0; it < 8; it++) cpasync16(sa + bdst[it], bptr[it], bsz[it]);
        CP_COMMIT();
    }

    for (int ck = 0; ck < nk; ck++) {
        if (ck + 1 < nk) {
            const uint32_t sa = smb + ((ck + 1) & 1) * STAGE_B;
            const int koff = (ck + 1) * 32;
#pragma unroll
            for (int it = 0; it < 4; it++)
                cpasync16(sa + adst[it], aptr[it] + koff, asz[it]);
#pragma unroll
            for (int it = 0; it < 8; it++)
                cpasync16(sa + bdst[it], bptr[it] + koff, bsz[it]);
            CP_COMMIT();
            CP_WAIT(1);
        } else {
            CP_WAIT(0);
        }
        __syncthreads();

        const float* As = sm + (ck & 1) * STAGE_FL;
        const float* Bs = As + A_FL;
#pragma unroll
        for (int ks = 0; ks < 4; ks++) {
            uint32_t af[4][4], bf[8][2];
#pragma unroll
            for (int mt = 0; mt < 4; mt++) {
                const float* p = As + (wm * 64 + mt * 16 + lg) * PITCH + ks * 8 + lt;
                af[mt][0] = __float_as_uint(p[0]);
                af[mt][1] = __float_as_uint(p[8 * PITCH]);
                af[mt][2] = __float_as_uint(p[4]);
                af[mt][3] = __float_as_uint(p[8 * PITCH + 4]);
            }
#pragma unroll
            for (int nt = 0; nt < 8; nt++) {
                const float* p = Bs + (wn * 64 + nt * 8 + lg) * PITCH + ks * 8 + lt;
                bf[nt][0] = __float_as_uint(p[0]);
                bf[nt][1] = __float_as_uint(p[4]);
            }
#pragma unroll
            for (int mt = 0; mt < 4; mt++)
#pragma unroll
                for (int nt = 0; nt < 8; nt++) mma8(acc[mt][nt], af[mt], bf[nt]);
        }
        __syncthreads();
    }

#pragma unroll
    for (int mt = 0; mt < 4; mt++) {
        const int r = m0 + wm * 64 + mt * 16 + lg;
#pragma unroll
        for (int nt = 0; nt < 8; nt++) {
            const int n = n0 + wn * 64 + nt * 8 + 2 * lt;
            float4 v = acc[mt][nt];
            if (DO_EXP) {
                v.x = __expf(v.x); v.y = __expf(v.y);
                v.z = __expf(v.z); v.w = __expf(v.w);
            }
            v = cvt4(v);
            if (n < NB) {
                if (r < MA)
                    *(float2*)(C + (long)r * ldc + n) = make_float2(v.x, v.y);
                if (r + 8 < MA)
                    *(float2*)(C + (long)(r + 8) * ldc + n) = make_float2(v.z, v.w);
            }
        }
    }
}

// ---------------- conv 3x3 SAME via implicit GEMM ----------------------------
// out[o][p] = sum_{kyx,c} wT[which][kyx][o][c] * inT[p+shift][c]
__global__ void __launch_bounds__(256, 1)
conv_mma(const float* __restrict__ attTe, const float* __restrict__ attTq,
         const float* __restrict__ wT, float* __restrict__ out)
{
    extern __shared__ float sm[];
    const uint32_t smb = s2u(sm);
    const int tid = threadIdx.x;
    const int lane = tid & 31, wid = tid >> 5;
    const int wm = wid >> 2, wn = wid & 3;
    const int lg = lane >> 2, lt = lane & 3;
    const int z = blockIdx.z;
    const int b = z & 15, which = z >> 4;
    const float* inT = (which ? attTq : attTe) + (long)b * N_PIX * CCH;
    const float* wbase = wT + (long)which * 9 * CCH * CCH;
    const int m0 = blockIdx.y * 128;   // out-channel block (512/128 = 4, exact)
    const int n0 = blockIdx.x * 256;   // pixel block (7 blocks cover 1600)

    const int lrow = tid >> 3;
    const int lf4  = tid & 7;

    uint32_t adst[4], aoff[4];
#pragma unroll
    for (int it = 0; it < 4; it++) {
        int row = lrow + it * 32;
        aoff[it] = (m0 + row) * CCH + lf4 * 4;
        adst[it] = row * (PITCH * 4) + lf4 * 16;
    }
    int py_[8], px_[8];
    bool pv_[8];
    uint32_t bdst[8];
#pragma unroll
    for (int it = 0; it < 8; it++) {
        int row = lrow + it * 32;
        int p = n0 + row;
        py_[it] = p / 40; px_[it] = p % 40;
        pv_[it] = (p < N_PIX);
        bdst[it] = A_FL * 4 + row * (PITCH * 4) + lf4 * 16;
    }

    float4 acc[4][8];
#pragma unroll
    for (int i = 0; i < 4; i++)
#pragma unroll
        for (int j = 0; j < 8; j++) acc[i][j] = make_float4(0.f, 0.f, 0.f, 0.f);

    const int nk = 144;   // 9 kyx * 16 c-chunks

    auto issue = [&](int ck, uint32_t sa) {
        const int kyx = ck >> 4;
        const int cc = (ck & 15) * 32;
        const int dy = kyx / 3 - 1, dx = kyx % 3 - 1;
        const float* wk = wbase + (long)kyx * (CCH * CCH) + cc;
#pragma unroll
        for (int it = 0; it < 4; it++)
            cpasync16(sa + adst[it], wk + aoff[it], 16u);
#pragma unroll
        for (int it = 0; it < 8; it++) {
            int ys = py_[it] + dy, xs = px_[it] + dx;
            bool ok = pv_[it] && (unsigned)ys < 40u && (unsigned)xs < 40u;
            const float* src = inT + (long)(ys * 40 + xs) * CCH + cc + lf4 * 4;
            cpasync16(sa + bdst[it], src, ok ? 16u : 0u);
        }
        CP_COMMIT();
    };

    issue(0, smb);
    for (int ck = 0; ck < nk; ck++) {
        if (ck + 1 < nk) {
            issue(ck + 1, smb + ((ck + 1) & 1) * STAGE_B);
            CP_WAIT(1);
        } else {
            CP_WAIT(0);
        }
        __syncthreads();

        const float* As = sm + (ck & 1) * STAGE_FL;
        const float* Bs = As + A_FL;
#pragma unroll
        for (int ks = 0; ks < 4; ks++) {
            uint32_t af[4][4], bf[8][2];
#pragma unroll
            for (int mt = 0; mt < 4; mt++) {
                const float* p = As + (wm * 64 + mt * 16 + lg) * PITCH + ks * 8 + lt;
                af[mt][0] = __float_as_uint(p[0]);
                af[mt][1] = __float_as_uint(p[8 * PITCH]);
                af[mt][2] = __float_as_uint(p[4]);
                af[mt][3] = __float_as_uint(p[8 * PITCH + 4]);
            }
#pragma unroll
            for (int nt = 0; nt < 8; nt++) {
                const float* p = Bs + (wn * 64 + nt * 8 + lg) * PITCH + ks * 8 + lt;
                bf[nt][0] = __float_as_uint(p[0]);
                bf[nt][1] = __float_as_uint(p[4]);
            }
#pragma unroll
            for (int mt = 0; mt < 4; mt++)
#pragma unroll
                for (int nt = 0; nt < 8; nt++) mma8(acc[mt][nt], af[mt], bf[nt]);
        }
        __syncthreads();
    }

    float* obase = out + ((long)b * 2 * CCH + (long)which * CCH) * N_PIX;
#pragma unroll
    for (int mt = 0; mt < 4; mt++) {
        const int r = m0 + wm * 64 + mt * 16 + lg;
#pragma unroll
        for (int nt = 0; nt < 8; nt++) {
            const int n = n0 + wn * 64 + nt * 8 + 2 * lt;
            if (n < N_PIX) {
                float4 v = acc[mt][nt];
                *(float2*)(obase + (long)r * N_PIX + n) = make_float2(v.x, v.y);
                *(float2*)(obase + (long)(r + 8) * N_PIX + n) = make_float2(v.z, v.w);
            }
        }
    }
}

// ---------------- generic batched transpose (tf32-rounding store) -----------
__global__ void transpose_kernel(const float* __restrict__ src,
                                 float* __restrict__ dst,
                                 int R, int C, long sstride, long dstride)
{
    __shared__ float t[32][33];
    src += (long)blockIdx.z * sstride;
    dst += (long)blockIdx.z * dstride;
    const int x0 = blockIdx.x * 32, y0 = blockIdx.y * 32;
    const int tx = threadIdx.x, ty = threadIdx.y;   // (32, 8)
#pragma unroll
    for (int r = 0; r < 32; r += 8)
        t[ty + r][tx] = src[(long)(y0 + ty + r) * C + x0 + tx];
    __syncthreads();
#pragma unroll
    for (int r = 0; r < 32; r += 8)
        dst[(long)(x0 + ty + r) * R + y0 + tx] = cvt1(t[tx][ty + r]);
}

// ---------------- row sums of E and Et ---------------------------------------
__global__ void rowsum_kernel(const float* __restrict__ E,
                              const float* __restrict__ Et,
                              float* __restrict__ rsE, float* __restrict__ rsEt)
{
    const long NN = (long)N_PIX * N_PIX;
    const float* src = (blockIdx.y ? Et : E) + (long)blockIdx.z * NN
                       + (long)blockIdx.x * N_PIX;
    float* dst = (blockIdx.y ? rsEt : rsE) + blockIdx.z * N_PIX + blockIdx.x;
    const int tid = threadIdx.x;   // 256
    float s = 0.f;
    for (int i = tid; i < N_PIX; i += 256) s += src[i];
    __shared__ float red[256];
    red[tid] = s;
    __syncthreads();
    for (int st = 128; st > 0; st >>= 1) {
        if (tid < st) red[tid] += red[tid + st];
        __syncthreads();
    }
    if (tid == 0) *dst = red[0];
}

__global__ void inv_kernel(float* __restrict__ a, float* __restrict__ b, int n)
{
    int i = blockIdx.x * 256 + threadIdx.x;
    if (i < n) { a[i] = 1.f / a[i]; b[i] = 1.f / b[i]; }
}

// esc = exemplar * invColsum(E)[i]; qsc = query * invRowsum(E)[i]  (tf32 out)
__global__ void scale_kernel(const float* __restrict__ ex,
                             const float* __restrict__ qu,
                             const float* __restrict__ invCs,
                             const float* __restrict__ invRs,
                             float* __restrict__ e2, float* __restrict__ q2)
{
    long idx = (long)blockIdx.x * 256 + threadIdx.x;
    if (idx >= (long)BATCH * CCH * N_PIX) return;
    int i = (int)(idx % N_PIX);
    int b = (int)(idx / ((long)CCH * N_PIX));
    e2[idx] = cvt1(ex[idx] * invCs[b * N_PIX + i]);
    q2[idx] = cvt1(qu[idx] * invRs[b * N_PIX + i]);
}

// ---------------- conv weights OIHW -> [which][kyx][o][c] (tf32) -------------
__global__ void wtrans_kernel(const float* __restrict__ w1,
                              const float* __restrict__ w2,
                              float* __restrict__ wT)
{
    long idx = (long)blockIdx.x * 256 + threadIdx.x;
    const long per = 9L * CCH * CCH;
    if (idx >= 2 * per) return;
    int c = (int)(idx & (CCH - 1));
    long t = idx >> 9;
    int o = (int)(t & (CCH - 1));
    long t2 = t >> 9;
    int kyx = (int)(t2 % 9);
    int which = (int)(t2 / 9);
    const float* w = which ? w2 : w1;
    wT[idx] = cvt1(w[((long)o * CCH + c) * 9 + kyx]);
}

// ---------------- 1x1 weights: copy w_q, w_e with tf32 rounding --------------
__global__ void w1cvt_kernel(const float* __restrict__ wq,
                             const float* __restrict__ we,
                             float* __restrict__ dst)
{
    int idx = blockIdx.x * 256 + threadIdx.x;
    if (idx >= 2 * CORR * CCH) return;
    const float* w = (idx < CORR * CCH) ? wq : we;
    dst[idx] = cvt1(w[idx < CORR * CCH ? idx : idx - CORR * CCH]);
}

// ---------------- launch ------------------------------------------------------
extern "C" void kernel_launch(void* const* d_in, const int* in_sizes, int n_in,
                              void* d_out, int out_size)
{
    const float* exemplar = (const float*)d_in[0];
    const float* query    = (const float*)d_in[1];
    const float* w_e      = (const float*)d_in[2];
    const float* w_q      = (const float*)d_in[3];
    const float* w_c1     = (const float*)d_in[4];
    const float* w_c2     = (const float*)d_in[5];
    float* out = (float*)d_out;

    float *inTe, *inTq, *qcorr, *ecorr, *E, *Et, *rsE, *rsEt,
          *esc, *qsc, *att_e, *att_q, *attTe, *attTq, *wT, *w1;
    cudaGetSymbolAddress((void**)&inTe,  g_inTe);
    cudaGetSymbolAddress((void**)&inTq,  g_inTq);
    cudaGetSymbolAddress((void**)&qcorr, g_qcorr);
    cudaGetSymbolAddress((void**)&ecorr, g_ecorr);
    cudaGetSymbolAddress((void**)&E,     g_E);
    cudaGetSymbolAddress((void**)&Et,    g_Et);
    cudaGetSymbolAddress((void**)&rsE,   g_rsE);
    cudaGetSymbolAddress((void**)&rsEt,  g_rsEt);
    cudaGetSymbolAddress((void**)&esc,   g_esc);
    cudaGetSymbolAddress((void**)&qsc,   g_qsc);
    cudaGetSymbolAddress((void**)&att_e, g_att_e);
    cudaGetSymbolAddress((void**)&att_q, g_att_q);
    cudaGetSymbolAddress((void**)&attTe, g_attTe);
    cudaGetSymbolAddress((void**)&attTq, g_attTq);
    cudaGetSymbolAddress((void**)&wT,    g_wT);
    cudaGetSymbolAddress((void**)&w1,    g_w1);

    cudaFuncSetAttribute(gemm_mma<false>,
                         cudaFuncAttributeMaxDynamicSharedMemorySize, SMEM_B);
    cudaFuncSetAttribute(gemm_mma<true>,
                         cudaFuncAttributeMaxDynamicSharedMemorySize, SMEM_B);
    cudaFuncSetAttribute(conv_mma,
                         cudaFuncAttributeMaxDynamicSharedMemorySize, SMEM_B);

    const long NN = (long)N_PIX * N_PIX;
    const long CN = (long)CCH * N_PIX;
    const long NK = (long)N_PIX * CORR;

    // weight re-layouts (tf32)
    wtrans_kernel<<<(unsigned)((2L * 9 * CCH * CCH + 255) / 256), 256>>>(w_c1, w_c2, wT);
    w1cvt_kernel<<<(2 * CORR * CCH + 255) / 256, 256>>>(w_q, w_e, w1);

    // input transposes [c][p] -> [p][c] (tf32)
    transpose_kernel<<<dim3(50, 16, BATCH), dim3(32, 8)>>>(exemplar, inTe,
                                                           CCH, N_PIX, CN, CN);
    transpose_kernel<<<dim3(50, 16, BATCH), dim3(32, 8)>>>(query, inTq,
                                                           CCH, N_PIX, CN, CN);

    // 1x1 projections: corr[p][o] = sum_c inT[p][c] * w[o][c]
    gemm_mma<false><<<dim3(1, 13, BATCH), 256, SMEM_B>>>(
        inTq, w1, qcorr, CCH, N_PIX, CORR, CORR, CN, 0L, NK);
    gemm_mma<false><<<dim3(1, 13, BATCH), 256, SMEM_B>>>(
        inTe, w1 + (long)CORR * CCH, ecorr, CCH, N_PIX, CORR, CORR, CN, 0L, NK);

    // E[n][m] = exp( sum_k ecorr[n][k] * qcorr[m][k] )
    gemm_mma<true><<<dim3(7, 13, BATCH), 256, SMEM_B>>>(
        ecorr, qcorr, E, CORR, N_PIX, N_PIX, N_PIX, NK, NK, NN);

    // Et = E^T
    transpose_kernel<<<dim3(50, 50, BATCH), dim3(32, 8)>>>(E, Et,
                                                           N_PIX, N_PIX, NN, NN);

    // row sums -> inverses -> scaled inputs
    rowsum_kernel<<<dim3(N_PIX, 2, BATCH), 256>>>(E, Et, rsE, rsEt);
    inv_kernel<<<(BATCH * N_PIX + 255) / 256, 256>>>(rsE, rsEt, BATCH * N_PIX);
    scale_kernel<<<(unsigned)(((long)BATCH * CCH * N_PIX + 255) / 256), 256>>>(
        exemplar, query, rsEt, rsE, esc, qsc);

    // query_att[c][j]    = sum_i esc[c][i] * E[j][i]
    gemm_mma<false><<<dim3(7, 4, BATCH), 256, SMEM_B>>>(
        esc, E, att_q, N_PIX, CCH, N_PIX, N_PIX, CN, NN, CN);
    // exemplar_att[c][j] = sum_i qsc[c][i] * Et[j][i]
    gemm_mma<false><<<dim3(7, 4, BATCH), 256, SMEM_B>>>(
        qsc, Et, att_e, N_PIX, CCH, N_PIX, N_PIX, CN, NN, CN);

    // transpose attention outputs to [pixel][channel] for conv
    transpose_kernel<<<dim3(50, 16, BATCH), dim3(32, 8)>>>(att_e, attTe,
                                                           CCH, N_PIX, CN, CN);
    transpose_kernel<<<dim3(50, 16, BATCH), dim3(32, 8)>>>(att_q, attTq,
                                                           CCH, N_PIX, CN, CN);

    // 3x3 SAME convs into concatenated output
    conv_mma<<<dim3(7, 4, 2 * BATCH), 256, SMEM_B>>>(attTe, attTq, wT, out);
}